// round 1
// baseline (speedup 1.0000x reference)
#include <cuda_runtime.h>
#include <cuda_bf16.h>
#include <cstdint>

// Problem constants
#define B_    256
#define T_    512
#define EMB_  512
#define HID_  1024
#define HEAD_ 100
#define NCLS_ 10
#define MTOT  (B_*T_)     // 131072 rows of the UX GEMM
#define BH    (B_*HID_)   // 262144

// ---------------- static device scratch (no allocations allowed) ------------
__device__ float    g_UX[T_*B_*HID_];   // [t][b][h] fp32, 512 MB
__device__ float    g_h [BH];           // final hidden state [b][h]
__device__ float    g_h2[BH];           // fallback double buffer
__device__ float    g_wdiag[HID_];
__device__ int      g_flag;             // 1 => W is diagonal
__device__ unsigned g_barcnt;           // fallback grid barrier counter

// ---------------- init / diagonal check -------------------------------------
__global__ void k_init() { g_flag = 1; g_barcnt = 0u; }

__global__ void k_check(const float* __restrict__ W) {
    int i = blockIdx.x;                       // row, grid = 1024
    for (int j = threadIdx.x; j < HID_; j += blockDim.x) {
        float v = W[(size_t)i * HID_ + j];
        if (j == i)            g_wdiag[i] = v;
        else if (v != 0.0f)    g_flag = 0;    // only-0 writes: race-free
    }
}

// ---------------- UX GEMM: fused gather + bf16-split HMMA -------------------
// C[m][h] = sum_e emb[ids[b*T+t]][e] * U[h][e],  m = t*256 + b
// bf16 split: x ~= xh + xl, U ~= Uh + Ul; C ~= xh*Uh + xh*Ul + xl*Uh (fp32 acc)
// CTA tile 128x128, BK=16, 8 warps (2x4), warp tile 64x32, m16n8k16.

__device__ __forceinline__ void ldsm4(unsigned& r0, unsigned& r1,
                                      unsigned& r2, unsigned& r3, unsigned addr) {
    asm volatile("ldmatrix.sync.aligned.m8n8.x4.shared.b16 {%0,%1,%2,%3},[%4];\n"
                 : "=r"(r0), "=r"(r1), "=r"(r2), "=r"(r3) : "r"(addr));
}

__device__ __forceinline__ void mma_bf16(float* c, const unsigned* a, const unsigned* b) {
    asm volatile(
        "mma.sync.aligned.m16n8k16.row.col.f32.bf16.bf16.f32 "
        "{%0,%1,%2,%3},{%4,%5,%6,%7},{%8,%9},{%0,%1,%2,%3};\n"
        : "+f"(c[0]), "+f"(c[1]), "+f"(c[2]), "+f"(c[3])
        : "r"(a[0]), "r"(a[1]), "r"(a[2]), "r"(a[3]), "r"(b[0]), "r"(b[1]));
}

// split 8 fp32 into hi/lo bf16 and store as one STS.128 each
__device__ __forceinline__ void split_store(__nv_bfloat16* hi_dst, __nv_bfloat16* lo_dst,
                                            float4 v0, float4 v1) {
    float v[8] = {v0.x, v0.y, v0.z, v0.w, v1.x, v1.y, v1.z, v1.w};
    unsigned h[4], l[4];
#pragma unroll
    for (int i = 0; i < 4; i++) {
        float a = v[2*i], b = v[2*i+1];
        __nv_bfloat16 ah = __float2bfloat16_rn(a), bh = __float2bfloat16_rn(b);
        float ar = a - __bfloat162float(ah);
        float br = b - __bfloat162float(bh);
        __nv_bfloat16 al = __float2bfloat16_rn(ar), bl = __float2bfloat16_rn(br);
        h[i] = (unsigned)__bfloat16_as_ushort(ah) | ((unsigned)__bfloat16_as_ushort(bh) << 16);
        l[i] = (unsigned)__bfloat16_as_ushort(al) | ((unsigned)__bfloat16_as_ushort(bl) << 16);
    }
    *reinterpret_cast<uint4*>(hi_dst) = make_uint4(h[0], h[1], h[2], h[3]);
    *reinterpret_cast<uint4*>(lo_dst) = make_uint4(l[0], l[1], l[2], l[3]);
}

#define SMS 24   // smem row stride in bf16 (48B, 16B aligned, conflict-light)

__global__ __launch_bounds__(256, 1)
void k_gemm(const int* __restrict__ ids, const float* __restrict__ emb,
            const float* __restrict__ U) {
    // [stage][0=Ah 1=Al 2=Bh 3=Bl][128*24] bf16 = 48 KB total
    __shared__ __align__(16) __nv_bfloat16 sm[2][4][128 * SMS];

    const int tid = threadIdx.x;
    const int m0 = blockIdx.y * 128, n0 = blockIdx.x * 128;

    // ---- global load mapping: thread owns (row r, half q): 8 floats / matrix
    const int r = tid >> 1, q = tid & 1;
    const int m  = m0 + r;
    const int id = ids[(m & 255) * T_ + (m >> 8)];       // gather index (fixed per thread)
    const float4* aptr = reinterpret_cast<const float4*>(emb + (size_t)id * EMB_) + q * 2;
    const float4* bptr = reinterpret_cast<const float4*>(U + (size_t)(n0 + r) * EMB_) + q * 2;

    const int lane = tid & 31, warp = tid >> 5;
    const int wm = warp >> 2, wn = warp & 3;

    float acc[4][4][4];
#pragma unroll
    for (int i = 0; i < 4; i++)
#pragma unroll
        for (int j = 0; j < 4; j++)
#pragma unroll
            for (int k = 0; k < 4; k++) acc[i][j][k] = 0.0f;

    // prologue: load iter 0 and stage it
    float4 ra0 = aptr[0], ra1 = aptr[1];
    float4 rb0 = bptr[0], rb1 = bptr[1];
    split_store(&sm[0][0][r * SMS + q * 8], &sm[0][1][r * SMS + q * 8], ra0, ra1);
    split_store(&sm[0][2][r * SMS + q * 8], &sm[0][3][r * SMS + q * 8], rb0, rb1);
    __syncthreads();

    for (int it = 0; it < 32; ++it) {            // K = 512 / BK 16
        if (it < 31) {                           // prefetch next tile to regs
            const float4* ap = aptr + (it + 1) * 4;
            const float4* bp = bptr + (it + 1) * 4;
            ra0 = ap[0]; ra1 = ap[1]; rb0 = bp[0]; rb1 = bp[1];
        }
        {   // ---- compute on stage it&1
            const int s = it & 1;
            unsigned base0 = (unsigned)__cvta_generic_to_shared(&sm[s][0][0]);
            unsigned base1 = (unsigned)__cvta_generic_to_shared(&sm[s][1][0]);
            unsigned base2 = (unsigned)__cvta_generic_to_shared(&sm[s][2][0]);
            unsigned base3 = (unsigned)__cvta_generic_to_shared(&sm[s][3][0]);

            unsigned Ah[4][4], Al[4][4], Bh[4][2], Bl[4][2];
            const int aoff0 = ((wm * 64 + (lane & 15)) * SMS + (lane >> 4) * 8) * 2;
#pragma unroll
            for (int mi = 0; mi < 4; mi++) {
                unsigned ad = aoff0 + mi * 16 * SMS * 2;
                ldsm4(Ah[mi][0], Ah[mi][1], Ah[mi][2], Ah[mi][3], base0 + ad);
                ldsm4(Al[mi][0], Al[mi][1], Al[mi][2], Al[mi][3], base1 + ad);
            }
            const int boff0 = ((wn * 32 + (lane & 7) + ((lane >> 4) << 3)) * SMS
                               + ((lane >> 3) & 1) * 8) * 2;
#pragma unroll
            for (int p = 0; p < 2; p++) {
                unsigned bd = boff0 + p * 16 * SMS * 2;
                ldsm4(Bh[2*p][0], Bh[2*p][1], Bh[2*p+1][0], Bh[2*p+1][1], base2 + bd);
                ldsm4(Bl[2*p][0], Bl[2*p][1], Bl[2*p+1][0], Bl[2*p+1][1], base3 + bd);
            }
#pragma unroll
            for (int mi = 0; mi < 4; mi++)
#pragma unroll
                for (int ni = 0; ni < 4; ni++) {
                    mma_bf16(acc[mi][ni], Ah[mi], Bh[ni]);   // hi*hi
                    mma_bf16(acc[mi][ni], Ah[mi], Bl[ni]);   // hi*lo
                    mma_bf16(acc[mi][ni], Al[mi], Bh[ni]);   // lo*hi
                }
        }
        if (it < 31) {
            const int s2 = (it + 1) & 1;
            split_store(&sm[s2][0][r * SMS + q * 8], &sm[s2][1][r * SMS + q * 8], ra0, ra1);
            split_store(&sm[s2][2][r * SMS + q * 8], &sm[s2][3][r * SMS + q * 8], rb0, rb1);
            __syncthreads();
        }
    }

    // ---- epilogue: fp32 accumulators -> g_UX
#pragma unroll
    for (int mi = 0; mi < 4; mi++) {
        int mrow = m0 + wm * 64 + mi * 16 + (lane >> 2);
#pragma unroll
        for (int ni = 0; ni < 4; ni++) {
            int h = n0 + wn * 32 + ni * 8 + (lane & 3) * 2;
            *reinterpret_cast<float2*>(&g_UX[(size_t)mrow * HID_ + h]) =
                make_float2(acc[mi][ni][0], acc[mi][ni][1]);
            *reinterpret_cast<float2*>(&g_UX[(size_t)(mrow + 8) * HID_ + h]) =
                make_float2(acc[mi][ni][2], acc[mi][ni][3]);
        }
    }
}

// ---------------- recurrence, diagonal fast path -----------------------------
__global__ void k_rec_diag(const float* __restrict__ Wb) {
    if (!g_flag) return;
    const int idx = blockIdx.x * blockDim.x + threadIdx.x;   // b*1024 + h
    const int h = idx & 1023;
    const float w = g_wdiag[h];
    const float bb = Wb[h];
    float hv = 0.0f;
    const float* ux = g_UX + idx;
#pragma unroll 8
    for (int t = 0; t < T_; ++t) {
        hv = fmaxf(fmaf(hv, w, bb + ux[(size_t)t * BH]), 0.0f);
    }
    g_h[idx] = hv;
}

// ---------------- recurrence, generic fallback (dormant in practice) --------
__global__ void k_rec_fb(const float* __restrict__ W, const float* __restrict__ Wb) {
    if (g_flag) return;
    const int tid = blockIdx.x * blockDim.x + threadIdx.x;
    const int NT = gridDim.x * blockDim.x;
    for (int t = 0; t < T_; ++t) {
        const float* cur = (t & 1) ? g_h2 : g_h;
        float*       nxt = (t & 1) ? g_h  : g_h2;   // t=511 writes g_h
        const float* ux  = g_UX + (size_t)t * BH;
        for (int o = tid; o < BH; o += NT) {
            int b = o >> 10, i = o & 1023;
            float s = Wb[i] + ux[o];
            if (t > 0) {
                const float* hr = cur + (b << 10);
                const float* wr = W + ((size_t)i << 10);
                for (int j = 0; j < HID_; ++j) s += hr[j] * wr[j];
            }
            nxt[o] = fmaxf(s, 0.0f);
        }
        // software grid barrier (grid = exactly 148 resident CTAs)
        __syncthreads();
        if (threadIdx.x == 0) {
            __threadfence();
            atomicAdd(&g_barcnt, 1u);
            while (atomicAdd(&g_barcnt, 0u) < 148u * (unsigned)(t + 1)) {}
        }
        __syncthreads();
    }
}

// ---------------- head: z = relu(h@h1^T + b1); out = z@h2^T + b2 -------------
__global__ void k_head(const float* __restrict__ h1w, const float* __restrict__ h1b,
                       const float* __restrict__ h2w, const float* __restrict__ h2b,
                       float* __restrict__ out) {
    __shared__ float hs[HID_];
    __shared__ float zs[HEAD_];
    const int b = blockIdx.x, tid = threadIdx.x;       // 256 blocks, 128 threads
    const float* hrow = g_h + (size_t)b * HID_;
    for (int k = tid; k < HID_; k += 128) hs[k] = hrow[k];
    __syncthreads();

    const int warp = tid >> 5, lane = tid & 31;
    for (int j = warp; j < HEAD_; j += 4) {
        float s = 0.0f;
        const float* w = h1w + (size_t)j * HID_;
        for (int k = lane; k < HID_; k += 32) s += hs[k] * w[k];
#pragma unroll
        for (int o = 16; o; o >>= 1) s += __shfl_xor_sync(0xffffffffu, s, o);
        if (lane == 0) zs[j] = fmaxf(s + h1b[j], 0.0f);
    }
    __syncthreads();

    for (int c = warp; c < NCLS_; c += 4) {
        float s = 0.0f;
        const float* w = h2w + (size_t)c * HEAD_;
        for (int j = lane; j < HEAD_; j += 32) s += zs[j] * w[j];
#pragma unroll
        for (int o = 16; o; o >>= 1) s += __shfl_xor_sync(0xffffffffu, s, o);
        if (lane == 0) out[b * NCLS_ + c] = s + h2b[c];
    }
}

// ---------------- launcher ---------------------------------------------------
extern "C" void kernel_launch(void* const* d_in, const int* in_sizes, int n_in,
                              void* d_out, int out_size) {
    const int*   ids = (const int*)  d_in[0];
    const float* emb = (const float*)d_in[1];
    const float* U   = (const float*)d_in[2];
    const float* W   = (const float*)d_in[3];
    const float* Wb  = (const float*)d_in[4];
    const float* h1w = (const float*)d_in[5];
    const float* h1b = (const float*)d_in[6];
    const float* h2w = (const float*)d_in[7];
    const float* h2b = (const float*)d_in[8];
    float* out = (float*)d_out;

    k_init<<<1, 1>>>();
    k_check<<<HID_, 256>>>(W);
    k_gemm<<<dim3(HID_ / 128, MTOT / 128), 256>>>(ids, emb, U);
    k_rec_diag<<<BH / 256, 256>>>(Wb);
    k_rec_fb<<<148, 256>>>(W, Wb);
    k_head<<<B_, 128>>>(h1w, h1b, h2w, h2b, out);
}

// round 2
// speedup vs baseline: 3.3041x; 3.3041x over previous
#include <cuda_runtime.h>
#include <cuda_bf16.h>
#include <cstdint>

// Problem constants
#define B_    256
#define T_    512
#define EMB_  512
#define HID_  1024
#define HEAD_ 100
#define NCLS_ 10
#define VOC_  32000
#define BH    (B_*HID_)   // 262144

// ---------------- static device scratch (no allocations allowed) ------------
__device__ float    g_proj[(size_t)VOC_*HID_];  // proj = emb_table @ U^T, 131 MB
__device__ float    g_h [BH];                   // final hidden state [b][h]
__device__ float    g_h2[BH];                   // fallback double buffer
__device__ float    g_wdiag[HID_];
__device__ int      g_flag;                     // 1 => W is diagonal
__device__ unsigned g_barcnt;                   // fallback grid barrier counter

// ---------------- init / diagonal check -------------------------------------
__global__ void k_init() { g_flag = 1; g_barcnt = 0u; }

__global__ void k_check(const float* __restrict__ W) {
    int i = blockIdx.x;                       // row, grid = 1024
    for (int j = threadIdx.x; j < HID_; j += blockDim.x) {
        float v = W[(size_t)i * HID_ + j];
        if (j == i)            g_wdiag[i] = v;
        else if (v != 0.0f)    g_flag = 0;    // only-0 writes: race-free
    }
}

// ---------------- proj GEMM: bf16-split HMMA ---------------------------------
// proj[v][h] = sum_e emb[v][e] * U[h][e]   (V=32000, H=1024, E=512)
// bf16 split: x ~= xh + xl, U ~= Uh + Ul; C ~= xh*Uh + xh*Ul + xl*Uh (fp32 acc)
// CTA tile 128x128, BK=16, 8 warps (2x4), warp tile 64x32, m16n8k16.

__device__ __forceinline__ void ldsm4(unsigned& r0, unsigned& r1,
                                      unsigned& r2, unsigned& r3, unsigned addr) {
    asm volatile("ldmatrix.sync.aligned.m8n8.x4.shared.b16 {%0,%1,%2,%3},[%4];\n"
                 : "=r"(r0), "=r"(r1), "=r"(r2), "=r"(r3) : "r"(addr));
}

__device__ __forceinline__ void mma_bf16(float* c, const unsigned* a, const unsigned* b) {
    asm volatile(
        "mma.sync.aligned.m16n8k16.row.col.f32.bf16.bf16.f32 "
        "{%0,%1,%2,%3},{%4,%5,%6,%7},{%8,%9},{%0,%1,%2,%3};\n"
        : "+f"(c[0]), "+f"(c[1]), "+f"(c[2]), "+f"(c[3])
        : "r"(a[0]), "r"(a[1]), "r"(a[2]), "r"(a[3]), "r"(b[0]), "r"(b[1]));
}

// split 8 fp32 into hi/lo bf16 and store as one STS.128 each
__device__ __forceinline__ void split_store(__nv_bfloat16* hi_dst, __nv_bfloat16* lo_dst,
                                            float4 v0, float4 v1) {
    float v[8] = {v0.x, v0.y, v0.z, v0.w, v1.x, v1.y, v1.z, v1.w};
    unsigned h[4], l[4];
#pragma unroll
    for (int i = 0; i < 4; i++) {
        float a = v[2*i], b = v[2*i+1];
        __nv_bfloat16 ah = __float2bfloat16_rn(a), bh = __float2bfloat16_rn(b);
        float ar = a - __bfloat162float(ah);
        float br = b - __bfloat162float(bh);
        __nv_bfloat16 al = __float2bfloat16_rn(ar), bl = __float2bfloat16_rn(br);
        h[i] = (unsigned)__bfloat16_as_ushort(ah) | ((unsigned)__bfloat16_as_ushort(bh) << 16);
        l[i] = (unsigned)__bfloat16_as_ushort(al) | ((unsigned)__bfloat16_as_ushort(bl) << 16);
    }
    *reinterpret_cast<uint4*>(hi_dst) = make_uint4(h[0], h[1], h[2], h[3]);
    *reinterpret_cast<uint4*>(lo_dst) = make_uint4(l[0], l[1], l[2], l[3]);
}

#define SMS 24   // smem row stride in bf16 (48B, 16B aligned, conflict-light)

__global__ __launch_bounds__(256, 1)
void k_gemm(const float* __restrict__ emb, const float* __restrict__ U) {
    // [stage][0=Ah 1=Al 2=Bh 3=Bl][128*24] bf16 = 48 KB total
    __shared__ __align__(16) __nv_bfloat16 sm[2][4][128 * SMS];

    const int tid = threadIdx.x;
    const int m0 = blockIdx.y * 128, n0 = blockIdx.x * 128;  // m0 < 32000 exactly

    // ---- global load mapping: thread owns (row r, half q): 8 floats / matrix
    const int r = tid >> 1, q = tid & 1;
    const float4* aptr = reinterpret_cast<const float4*>(emb + (size_t)(m0 + r) * EMB_) + q * 2;
    const float4* bptr = reinterpret_cast<const float4*>(U + (size_t)(n0 + r) * EMB_) + q * 2;

    const int lane = tid & 31, warp = tid >> 5;
    const int wm = warp >> 2, wn = warp & 3;

    float acc[4][4][4];
#pragma unroll
    for (int i = 0; i < 4; i++)
#pragma unroll
        for (int j = 0; j < 4; j++)
#pragma unroll
            for (int k = 0; k < 4; k++) acc[i][j][k] = 0.0f;

    // prologue: load iter 0 and stage it
    float4 ra0 = aptr[0], ra1 = aptr[1];
    float4 rb0 = bptr[0], rb1 = bptr[1];
    split_store(&sm[0][0][r * SMS + q * 8], &sm[0][1][r * SMS + q * 8], ra0, ra1);
    split_store(&sm[0][2][r * SMS + q * 8], &sm[0][3][r * SMS + q * 8], rb0, rb1);
    __syncthreads();

    for (int it = 0; it < 32; ++it) {            // K = 512 / BK 16
        if (it < 31) {                           // prefetch next tile to regs
            const float4* ap = aptr + (it + 1) * 4;
            const float4* bp = bptr + (it + 1) * 4;
            ra0 = ap[0]; ra1 = ap[1]; rb0 = bp[0]; rb1 = bp[1];
        }
        {   // ---- compute on stage it&1
            const int s = it & 1;
            unsigned base0 = (unsigned)__cvta_generic_to_shared(&sm[s][0][0]);
            unsigned base1 = (unsigned)__cvta_generic_to_shared(&sm[s][1][0]);
            unsigned base2 = (unsigned)__cvta_generic_to_shared(&sm[s][2][0]);
            unsigned base3 = (unsigned)__cvta_generic_to_shared(&sm[s][3][0]);

            unsigned Ah[4][4], Al[4][4], Bh[4][2], Bl[4][2];
            const int aoff0 = ((wm * 64 + (lane & 15)) * SMS + (lane >> 4) * 8) * 2;
#pragma unroll
            for (int mi = 0; mi < 4; mi++) {
                unsigned ad = aoff0 + mi * 16 * SMS * 2;
                ldsm4(Ah[mi][0], Ah[mi][1], Ah[mi][2], Ah[mi][3], base0 + ad);
                ldsm4(Al[mi][0], Al[mi][1], Al[mi][2], Al[mi][3], base1 + ad);
            }
            const int boff0 = ((wn * 32 + (lane & 7) + ((lane >> 4) << 3)) * SMS
                               + ((lane >> 3) & 1) * 8) * 2;
#pragma unroll
            for (int p = 0; p < 2; p++) {
                unsigned bd = boff0 + p * 16 * SMS * 2;
                ldsm4(Bh[2*p][0], Bh[2*p][1], Bh[2*p+1][0], Bh[2*p+1][1], base2 + bd);
                ldsm4(Bl[2*p][0], Bl[2*p][1], Bl[2*p+1][0], Bl[2*p+1][1], base3 + bd);
            }
#pragma unroll
            for (int mi = 0; mi < 4; mi++)
#pragma unroll
                for (int ni = 0; ni < 4; ni++) {
                    mma_bf16(acc[mi][ni], Ah[mi], Bh[ni]);   // hi*hi
                    mma_bf16(acc[mi][ni], Ah[mi], Bl[ni]);   // hi*lo
                    mma_bf16(acc[mi][ni], Al[mi], Bh[ni]);   // lo*hi
                }
        }
        if (it < 31) {
            const int s2 = (it + 1) & 1;
            split_store(&sm[s2][0][r * SMS + q * 8], &sm[s2][1][r * SMS + q * 8], ra0, ra1);
            split_store(&sm[s2][2][r * SMS + q * 8], &sm[s2][3][r * SMS + q * 8], rb0, rb1);
            __syncthreads();
        }
    }

    // ---- epilogue: fp32 accumulators -> g_proj
#pragma unroll
    for (int mi = 0; mi < 4; mi++) {
        int mrow = m0 + wm * 64 + mi * 16 + (lane >> 2);
#pragma unroll
        for (int ni = 0; ni < 4; ni++) {
            int h = n0 + wn * 32 + ni * 8 + (lane & 3) * 2;
            *reinterpret_cast<float2*>(&g_proj[(size_t)mrow * HID_ + h]) =
                make_float2(acc[mi][ni][0], acc[mi][ni][1]);
            *reinterpret_cast<float2*>(&g_proj[(size_t)(mrow + 8) * HID_ + h]) =
                make_float2(acc[mi][ni][2], acc[mi][ni][3]);
        }
    }
}

// ---------------- recurrence, diagonal fast path -----------------------------
// h_t[b,h] = relu(w[h]*h_{t-1}[b,h] + b[h] + proj[ids[b,t]][h])
__global__ void k_rec_diag(const int* __restrict__ ids, const float* __restrict__ Wb) {
    if (!g_flag) return;
    const int idx = blockIdx.x * blockDim.x + threadIdx.x;   // b*1024 + h
    const int h = idx & 1023;
    const int b = idx >> 10;
    const float w = g_wdiag[h];
    const float bb = Wb[h];
    const int* idrow = ids + b * T_;
    float hv = 0.0f;
#pragma unroll 8
    for (int t = 0; t < T_; ++t) {
        int id = __ldg(&idrow[t]);                      // uniform per warp
        float ux = __ldg(&g_proj[(size_t)id * HID_ + h]);
        hv = fmaxf(fmaf(hv, w, bb + ux), 0.0f);
    }
    g_h[idx] = hv;
}

// ---------------- recurrence, generic fallback (dormant in practice) --------
__global__ void k_rec_fb(const int* __restrict__ ids,
                         const float* __restrict__ W, const float* __restrict__ Wb) {
    if (g_flag) return;
    const int tid = blockIdx.x * blockDim.x + threadIdx.x;
    const int NT = gridDim.x * blockDim.x;
    for (int t = 0; t < T_; ++t) {
        const float* cur = (t & 1) ? g_h2 : g_h;
        float*       nxt = (t & 1) ? g_h  : g_h2;   // t=511 writes g_h
        for (int o = tid; o < BH; o += NT) {
            int b = o >> 10, i = o & 1023;
            int id = ids[b * T_ + t];
            float s = Wb[i] + g_proj[(size_t)id * HID_ + i];
            if (t > 0) {
                const float* hr = cur + (b << 10);
                const float* wr = W + ((size_t)i << 10);
                for (int j = 0; j < HID_; ++j) s += hr[j] * wr[j];
            }
            nxt[o] = fmaxf(s, 0.0f);
        }
        // software grid barrier (grid = exactly 148 resident CTAs)
        __syncthreads();
        if (threadIdx.x == 0) {
            __threadfence();
            atomicAdd(&g_barcnt, 1u);
            while (atomicAdd(&g_barcnt, 0u) < 148u * (unsigned)(t + 1)) {}
        }
        __syncthreads();
    }
}

// ---------------- head: z = relu(h@h1^T + b1); out = z@h2^T + b2 -------------
__global__ void k_head(const float* __restrict__ h1w, const float* __restrict__ h1b,
                       const float* __restrict__ h2w, const float* __restrict__ h2b,
                       float* __restrict__ out) {
    __shared__ float hs[HID_];
    __shared__ float zs[HEAD_];
    const int b = blockIdx.x, tid = threadIdx.x;       // 256 blocks, 128 threads
    const float* hrow = g_h + (size_t)b * HID_;
    for (int k = tid; k < HID_; k += 128) hs[k] = hrow[k];
    __syncthreads();

    const int warp = tid >> 5, lane = tid & 31;
    for (int j = warp; j < HEAD_; j += 4) {
        float s = 0.0f;
        const float* w = h1w + (size_t)j * HID_;
        for (int k = lane; k < HID_; k += 32) s += hs[k] * w[k];
#pragma unroll
        for (int o = 16; o; o >>= 1) s += __shfl_xor_sync(0xffffffffu, s, o);
        if (lane == 0) zs[j] = fmaxf(s + h1b[j], 0.0f);
    }
    __syncthreads();

    for (int c = warp; c < NCLS_; c += 4) {
        float s = 0.0f;
        const float* w = h2w + (size_t)c * HEAD_;
        for (int j = lane; j < HEAD_; j += 32) s += zs[j] * w[j];
#pragma unroll
        for (int o = 16; o; o >>= 1) s += __shfl_xor_sync(0xffffffffu, s, o);
        if (lane == 0) out[b * NCLS_ + c] = s + h2b[c];
    }
}

// ---------------- launcher ---------------------------------------------------
extern "C" void kernel_launch(void* const* d_in, const int* in_sizes, int n_in,
                              void* d_out, int out_size) {
    const int*   ids = (const int*)  d_in[0];
    const float* emb = (const float*)d_in[1];
    const float* U   = (const float*)d_in[2];
    const float* W   = (const float*)d_in[3];
    const float* Wb  = (const float*)d_in[4];
    const float* h1w = (const float*)d_in[5];
    const float* h1b = (const float*)d_in[6];
    const float* h2w = (const float*)d_in[7];
    const float* h2b = (const float*)d_in[8];
    float* out = (float*)d_out;

    k_init<<<1, 1>>>();
    k_check<<<HID_, 256>>>(W);
    k_gemm<<<dim3(HID_ / 128, VOC_ / 128), 256>>>(emb, U);   // 8 x 250 CTAs
    k_rec_diag<<<BH / 256, 256>>>(ids, Wb);
    k_rec_fb<<<148, 256>>>(ids, W, Wb);
    k_head<<<B_, 128>>>(h1w, h1b, h2w, h2b, out);
}

// round 4
// speedup vs baseline: 3.3884x; 1.0255x over previous
#include <cuda_runtime.h>
#include <cuda_bf16.h>
#include <cstdint>

// Problem constants
#define B_    256
#define T_    512
#define EMB_  512
#define HID_  1024
#define HEAD_ 100
#define NCLS_ 10
#define VOC_  32000
#define BH    (B_*HID_)

// ---------------- static device scratch -------------------------------------
__device__ float         g_proj[(size_t)VOC_*HID_];    // emb @ U^T, 131 MB
__device__ __nv_bfloat16 g_embh[(size_t)VOC_*EMB_];
__device__ __nv_bfloat16 g_embl[(size_t)VOC_*EMB_];
__device__ __nv_bfloat16 g_Uh[HID_*EMB_];
__device__ __nv_bfloat16 g_Ul[HID_*EMB_];
__device__ float    g_h [BH];
__device__ float    g_h2[BH];
__device__ float    g_wdiag[HID_];
__device__ int      g_flag;
__device__ unsigned g_barcnt;

// ---------------- init / diagonal check -------------------------------------
__global__ void k_init() { g_flag = 1; g_barcnt = 0u; }

__global__ void k_check(const float* __restrict__ W) {
    int i = blockIdx.x;
    for (int j = threadIdx.x; j < HID_; j += blockDim.x) {
        float v = W[(size_t)i * HID_ + j];
        if (j == i)         g_wdiag[i] = v;
        else if (v != 0.0f) g_flag = 0;
    }
}

// ---------------- fp32 -> bf16 hi/lo split (identical values to R2's in-loop split)
__global__ void k_split(const float* __restrict__ src, __nv_bfloat16* __restrict__ hi,
                        __nv_bfloat16* __restrict__ lo, int n4) {
    int i = blockIdx.x * blockDim.x + threadIdx.x;
    if (i >= n4) return;
    float4 v = __ldg(reinterpret_cast<const float4*>(src) + i);
    float vv[4] = {v.x, v.y, v.z, v.w};
    unsigned hu[2], lu[2];
#pragma unroll
    for (int p = 0; p < 2; p++) {
        __nv_bfloat16 h0 = __float2bfloat16_rn(vv[2*p]);
        __nv_bfloat16 h1 = __float2bfloat16_rn(vv[2*p+1]);
        __nv_bfloat16 l0 = __float2bfloat16_rn(vv[2*p]   - __bfloat162float(h0));
        __nv_bfloat16 l1 = __float2bfloat16_rn(vv[2*p+1] - __bfloat162float(h1));
        hu[p] = (unsigned)__bfloat16_as_ushort(h0) | ((unsigned)__bfloat16_as_ushort(h1) << 16);
        lu[p] = (unsigned)__bfloat16_as_ushort(l0) | ((unsigned)__bfloat16_as_ushort(l1) << 16);
    }
    *reinterpret_cast<uint2*>(hi + 4*(size_t)i) = make_uint2(hu[0], hu[1]);
    *reinterpret_cast<uint2*>(lo + 4*(size_t)i) = make_uint2(lu[0], lu[1]);
}

// ---------------- mma/ldsm/cp.async helpers ----------------------------------
__device__ __forceinline__ void ldsm4(unsigned& r0, unsigned& r1,
                                      unsigned& r2, unsigned& r3, unsigned addr) {
    asm volatile("ldmatrix.sync.aligned.m8n8.x4.shared.b16 {%0,%1,%2,%3},[%4];\n"
                 : "=r"(r0), "=r"(r1), "=r"(r2), "=r"(r3) : "r"(addr));
}
__device__ __forceinline__ void mma_bf16(float* c, const unsigned* a, const unsigned* b) {
    asm volatile(
        "mma.sync.aligned.m16n8k16.row.col.f32.bf16.bf16.f32 "
        "{%0,%1,%2,%3},{%4,%5,%6,%7},{%8,%9},{%0,%1,%2,%3};\n"
        : "+f"(c[0]), "+f"(c[1]), "+f"(c[2]), "+f"(c[3])
        : "r"(a[0]), "r"(a[1]), "r"(a[2]), "r"(a[3]), "r"(b[0]), "r"(b[1]));
}
__device__ __forceinline__ void cp16(unsigned dst, const void* src) {
    asm volatile("cp.async.cg.shared.global [%0], [%1], 16;\n" :: "r"(dst), "l"(src) : "memory");
}
__device__ __forceinline__ void cp_commit() {
    asm volatile("cp.async.commit_group;\n" ::: "memory");
}
template<int N> __device__ __forceinline__ void cp_wait() {
    asm volatile("cp.async.wait_group %0;\n" :: "n"(N) : "memory");
}

// GEMM geometry: CTA 128x128, BK=16, 4-stage cp.async pipeline, 8 warps (2x4),
// warp tile 64x32, 3-term bf16 split: AhBh + AhBl + AlBh (fp32 accumulate).
#define SMS 24                                   // smem row stride in bf16
#define T_BYTES (128*SMS*2)                      // 6144 B per tensor per stage
#define STG_BYTES (4*T_BYTES)                    // 24576 B per stage
#define NSTG 4
#define SMEM_TOTAL (NSTG*STG_BYTES)              // 96 KB

__global__ void __launch_bounds__(256, 1)
k_gemm(const __nv_bfloat16* __restrict__ Ahg, const __nv_bfloat16* __restrict__ Alg,
       const __nv_bfloat16* __restrict__ Bhg, const __nv_bfloat16* __restrict__ Blg) {
    extern __shared__ __align__(16) __nv_bfloat16 smem_dyn[];
    const unsigned sb = (unsigned)__cvta_generic_to_shared(smem_dyn);

    const int tid = threadIdx.x;
    const int m0 = blockIdx.y * 128, n0 = blockIdx.x * 128;
    const int r = tid >> 1, q = tid & 1;
    const unsigned doff = (unsigned)(r * SMS + q * 8) * 2;  // byte off within tensor

    const __nv_bfloat16* a_h = Ahg + (size_t)(m0 + r) * EMB_ + q * 8;
    const __nv_bfloat16* a_l = Alg + (size_t)(m0 + r) * EMB_ + q * 8;
    const __nv_bfloat16* b_h = Bhg + (size_t)(n0 + r) * EMB_ + q * 8;
    const __nv_bfloat16* b_l = Blg + (size_t)(n0 + r) * EMB_ + q * 8;

    const int lane = tid & 31, warp = tid >> 5;
    const int wm = warp >> 2, wn = warp & 3;

    float acc[4][4][4];
#pragma unroll
    for (int i = 0; i < 4; i++)
#pragma unroll
        for (int j = 0; j < 4; j++)
#pragma unroll
            for (int k = 0; k < 4; k++) acc[i][j][k] = 0.0f;

    auto load_stage = [&](int s, int c) {
        unsigned base = sb + s * STG_BYTES + doff;
        const int k0 = c * 16;
        cp16(base,               a_h + k0);
        cp16(base + 1*T_BYTES,   a_l + k0);
        cp16(base + 2*T_BYTES,   b_h + k0);
        cp16(base + 3*T_BYTES,   b_l + k0);
        cp_commit();
    };

    load_stage(0, 0);
    load_stage(1, 1);
    load_stage(2, 2);

    const int aoff0 = ((wm * 64 + (lane & 15)) * SMS + (lane >> 4) * 8) * 2;
    const int boff0 = ((wn * 32 + (lane & 7) + ((lane >> 4) << 3)) * SMS
                       + ((lane >> 3) & 1) * 8) * 2;

    for (int it = 0; it < 32; ++it) {
        if (it < 30)       cp_wait<2>();
        else if (it == 30) cp_wait<1>();
        else               cp_wait<0>();
        __syncthreads();
        if (it + 3 < 32) load_stage((it + 3) & 3, it + 3);

        const unsigned base = sb + (it & 3) * STG_BYTES;
        unsigned Ah[4][4], Al[4][4], Bh[4][2], Bl[4][2];
#pragma unroll
        for (int mi = 0; mi < 4; mi++) {
            unsigned ad = base + aoff0 + mi * 16 * SMS * 2;
            ldsm4(Ah[mi][0], Ah[mi][1], Ah[mi][2], Ah[mi][3], ad);
            ldsm4(Al[mi][0], Al[mi][1], Al[mi][2], Al[mi][3], ad + T_BYTES);
        }
#pragma unroll
        for (int p = 0; p < 2; p++) {
            unsigned bd = base + 2*T_BYTES + boff0 + p * 16 * SMS * 2;
            ldsm4(Bh[2*p][0], Bh[2*p][1], Bh[2*p+1][0], Bh[2*p+1][1], bd);
            ldsm4(Bl[2*p][0], Bl[2*p][1], Bl[2*p+1][0], Bl[2*p+1][1], bd + T_BYTES);
        }
#pragma unroll
        for (int mi = 0; mi < 4; mi++)
#pragma unroll
            for (int ni = 0; ni < 4; ni++) {
                mma_bf16(acc[mi][ni], Ah[mi], Bh[ni]);   // hi*hi
                mma_bf16(acc[mi][ni], Ah[mi], Bl[ni]);   // hi*lo
                mma_bf16(acc[mi][ni], Al[mi], Bh[ni]);   // lo*hi
            }
    }

    // ---- epilogue: fp32 accumulators -> g_proj
#pragma unroll
    for (int mi = 0; mi < 4; mi++) {
        int mrow = m0 + wm * 64 + mi * 16 + (lane >> 2);
#pragma unroll
        for (int ni = 0; ni < 4; ni++) {
            int h = n0 + wn * 32 + ni * 8 + (lane & 3) * 2;
            *reinterpret_cast<float2*>(&g_proj[(size_t)mrow * HID_ + h]) =
                make_float2(acc[mi][ni][0], acc[mi][ni][1]);
            *reinterpret_cast<float2*>(&g_proj[(size_t)(mrow + 8) * HID_ + h]) =
                make_float2(acc[mi][ni][2], acc[mi][ni][3]);
        }
    }
}

// ---------------- recurrence, diagonal fast path (float4) -------------------
__global__ void k_rec_diag(const int* __restrict__ ids, const float* __restrict__ Wb) {
    if (!g_flag) return;
    const int idx = blockIdx.x * blockDim.x + threadIdx.x;   // BH/4 threads
    const int h4 = (idx & 255) << 2;
    const int b  = idx >> 8;
    const float4 w  = *reinterpret_cast<const float4*>(&g_wdiag[h4]);
    const float4 bb = __ldg(reinterpret_cast<const float4*>(&Wb[h4]));
    const int* idrow = ids + b * T_;
    float4 hv = make_float4(0.f, 0.f, 0.f, 0.f);
#pragma unroll 4
    for (int t = 0; t < T_; ++t) {
        int id = __ldg(&idrow[t]);
        float4 ux = __ldg(reinterpret_cast<const float4*>(&g_proj[(size_t)id * HID_ + h4]));
        hv.x = fmaxf(fmaf(hv.x, w.x, bb.x + ux.x), 0.f);
        hv.y = fmaxf(fmaf(hv.y, w.y, bb.y + ux.y), 0.f);
        hv.z = fmaxf(fmaf(hv.z, w.z, bb.z + ux.z), 0.f);
        hv.w = fmaxf(fmaf(hv.w, w.w, bb.w + ux.w), 0.f);
    }
    *reinterpret_cast<float4*>(&g_h[((size_t)b << 10) + h4]) = hv;
}

// ---------------- recurrence, generic fallback (dormant in practice) --------
__global__ void k_rec_fb(const int* __restrict__ ids,
                         const float* __restrict__ W, const float* __restrict__ Wb) {
    if (g_flag) return;
    const int tid = blockIdx.x * blockDim.x + threadIdx.x;
    const int NT = gridDim.x * blockDim.x;
    for (int t = 0; t < T_; ++t) {
        const float* cur = (t & 1) ? g_h2 : g_h;
        float*       nxt = (t & 1) ? g_h  : g_h2;
        for (int o = tid; o < BH; o += NT) {
            int b = o >> 10, i = o & 1023;
            int id = ids[b * T_ + t];
            float s = Wb[i] + g_proj[(size_t)id * HID_ + i];
            if (t > 0) {
                const float* hr = cur + (b << 10);
                const float* wr = W + ((size_t)i << 10);
                for (int j = 0; j < HID_; ++j) s += hr[j] * wr[j];
            }
            nxt[o] = fmaxf(s, 0.0f);
        }
        __syncthreads();
        if (threadIdx.x == 0) {
            __threadfence();
            atomicAdd(&g_barcnt, 1u);
            while (atomicAdd(&g_barcnt, 0u) < 148u * (unsigned)(t + 1)) {}
        }
        __syncthreads();
    }
}

// ---------------- head ------------------------------------------------------
__global__ void k_head(const float* __restrict__ h1w, const float* __restrict__ h1b,
                       const float* __restrict__ h2w, const float* __restrict__ h2b,
                       float* __restrict__ out) {
    __shared__ float hs[HID_];
    __shared__ float zs[HEAD_];
    const int b = blockIdx.x, tid = threadIdx.x;
    const float* hrow = g_h + (size_t)b * HID_;
    for (int k = tid; k < HID_; k += 128) hs[k] = hrow[k];
    __syncthreads();

    const int warp = tid >> 5, lane = tid & 31;
    for (int j = warp; j < HEAD_; j += 4) {
        float s = 0.0f;
        const float* w = h1w + (size_t)j * HID_;
        for (int k = lane; k < HID_; k += 32) s += hs[k] * w[k];
#pragma unroll
        for (int o = 16; o; o >>= 1) s += __shfl_xor_sync(0xffffffffu, s, o);
        if (lane == 0) zs[j] = fmaxf(s + h1b[j], 0.0f);
    }
    __syncthreads();

    for (int c = warp; c < NCLS_; c += 4) {
        float s = 0.0f;
        const float* w = h2w + (size_t)c * HEAD_;
        for (int j = lane; j < HEAD_; j += 32) s += zs[j] * w[j];
#pragma unroll
        for (int o = 16; o; o >>= 1) s += __shfl_xor_sync(0xffffffffu, s, o);
        if (lane == 0) out[b * NCLS_ + c] = s + h2b[c];
    }
}

// ---------------- launcher ---------------------------------------------------
extern "C" void kernel_launch(void* const* d_in, const int* in_sizes, int n_in,
                              void* d_out, int out_size) {
    const int*   ids = (const int*)  d_in[0];
    const float* emb = (const float*)d_in[1];
    const float* U   = (const float*)d_in[2];
    const float* W   = (const float*)d_in[3];
    const float* Wb  = (const float*)d_in[4];
    const float* h1w = (const float*)d_in[5];
    const float* h1b = (const float*)d_in[6];
    const float* h2w = (const float*)d_in[7];
    const float* h2b = (const float*)d_in[8];
    float* out = (float*)d_out;

    cudaFuncSetAttribute(k_gemm, cudaFuncAttributeMaxDynamicSharedMemorySize, SMEM_TOTAL);

    __nv_bfloat16 *embh, *embl, *uh, *ul;
    cudaGetSymbolAddress((void**)&embh, g_embh);
    cudaGetSymbolAddress((void**)&embl, g_embl);
    cudaGetSymbolAddress((void**)&uh,   g_Uh);
    cudaGetSymbolAddress((void**)&ul,   g_Ul);

    k_init<<<1, 1>>>();
    k_check<<<HID_, 256>>>(W);
    k_split<<<(VOC_*EMB_/4 + 255)/256, 256>>>(emb, embh, embl, VOC_*EMB_/4);
    k_split<<<(HID_*EMB_/4 + 255)/256, 256>>>(U, uh, ul, HID_*EMB_/4);
    k_gemm<<<dim3(HID_/128, VOC_/128), 256, SMEM_TOTAL>>>(embh, embl, uh, ul);
    k_rec_diag<<<BH/4/256, 256>>>(ids, Wb);
    k_rec_fb<<<148, 256>>>(ids, W, Wb);
    k_head<<<B_, 128>>>(h1w, h1b, h2w, h2b, out);
}